// round 6
// baseline (speedup 1.0000x reference)
#include <cuda_runtime.h>
#include <cuda_bf16.h>
#include <math.h>
#include <stdint.h>

// ---------------------------------------------------------------------------
// Problem constants
// ---------------------------------------------------------------------------
#define NMAX   50176            // padded (50000 real)
#define EMAX   800000
#define ETMAX  (NMAX + EMAX)
#define F1     128
#define H1     4
#define OC2    32
#define WSTR   68               // padded uint32 row stride for B tiles in SMEM

// ---------------------------------------------------------------------------
// Scratch (device globals)
// ---------------------------------------------------------------------------
__device__ __align__(16) float    g_h1 [NMAX * F1];
__device__ __align__(16) float    g_o1 [NMAX * F1];
__device__ __align__(16) float    g_h2 [NMAX * OC2];
__device__ __align__(16) float    g_es1[NMAX * H1];
__device__ __align__(16) float    g_ed1[NMAX * H1];
__device__ __align__(16) float    g_es2[NMAX];
__device__ __align__(16) float    g_ed2[NMAX];
__device__ __align__(16) uint32_t g_xhi[NMAX * 64];   // bf16x2-packed hi of x
__device__ __align__(16) uint32_t g_xlo[NMAX * 64];   // bf16x2-packed lo of x
__device__ __align__(16) uint32_t g_whi[128 * WSTR];  // W1^T hi, n-major padded
__device__ __align__(16) uint32_t g_wlo[128 * WSTR];  // W1^T lo
__device__ int g_deg[NMAX];
__device__ int g_rowptr[NMAX + 1];
__device__ int g_cursor[NMAX];
__device__ int g_csr_src[ETMAX];

static inline int cdiv(int a, int b) { return (a + b - 1) / b; }

// ---------------------------------------------------------------------------
// Preprocessing
// ---------------------------------------------------------------------------
__device__ __forceinline__ int block_detect_i64(const int* ei) {
    int any = 0;
    #pragma unroll 8
    for (int k = 1; k < 128; k += 2) any |= ei[k];
    return (any == 0) ? 1 : 0;
}

__global__ void deg_kernel(const int* __restrict__ ei, int E, int n,
                           int* __restrict__ deg) {
    __shared__ int s64;
    if (threadIdx.x == 0) s64 = block_detect_i64(ei);
    __syncthreads();
    int i = blockIdx.x * blockDim.x + threadIdx.x;
    if (i >= E + n) return;
    int d;
    if (i < E) {
        d = s64 ? (int)((const long long*)ei)[(long long)E + i] : ei[E + i];
    } else {
        d = i - E;
    }
    atomicAdd(&deg[d], 1);
}

// Single-block two-pass scan: deg -> rowptr/cursor
__global__ void scan_kernel(const int* __restrict__ deg,
                            int* __restrict__ rowptr,
                            int* __restrict__ cursor, int n) {
    __shared__ int wsum[32];
    int t = threadIdx.x;
    int ipt = (n + 1023) >> 10;
    int start = t * ipt;
    int s = 0;
    for (int i = 0; i < ipt; i++) {
        int idx = start + i;
        if (idx < n) s += deg[idx];
    }
    int lane = t & 31, w = t >> 5;
    int v = s;
    #pragma unroll
    for (int m = 1; m < 32; m <<= 1) {
        int o = __shfl_up_sync(0xFFFFFFFF, v, m);
        if (lane >= m) v += o;
    }
    if (lane == 31) wsum[w] = v;
    __syncthreads();
    if (w == 0) {
        int x = wsum[lane];
        #pragma unroll
        for (int m = 1; m < 32; m <<= 1) {
            int o = __shfl_up_sync(0xFFFFFFFF, x, m);
            if (lane >= m) x += o;
        }
        wsum[lane] = x;
    }
    __syncthreads();
    int excl = (v - s) + (w > 0 ? wsum[w - 1] : 0);
    int run = excl;
    for (int i = 0; i < ipt; i++) {
        int idx = start + i;
        if (idx < n) {
            rowptr[idx] = run;
            cursor[idx] = run;
            run += deg[idx];
        }
    }
    if (t == 0) rowptr[n] = wsum[31];
}

__global__ void scatter_kernel(const int* __restrict__ ei, int E, int n,
                               int* __restrict__ cursor,
                               int* __restrict__ csr_src) {
    __shared__ int s64;
    if (threadIdx.x == 0) s64 = block_detect_i64(ei);
    __syncthreads();
    int i = blockIdx.x * blockDim.x + threadIdx.x;
    if (i >= E + n) return;
    int s, d;
    if (i < E) {
        if (s64) {
            const long long* p = (const long long*)ei;
            s = (int)p[i];
            d = (int)p[(long long)E + i];
        } else {
            s = ei[i];
            d = ei[E + i];
        }
    } else {
        s = i - E;
        d = i - E;
    }
    int p = atomicAdd(&cursor[d], 1);
    csr_src[p] = s;
}

// ---------------------------------------------------------------------------
// x -> (hi, lo) bf16x2-packed rows
// ---------------------------------------------------------------------------
__device__ __forceinline__ uint32_t pack_bf2(float a, float b) {
    __nv_bfloat16 ha = __float2bfloat16(a), hb = __float2bfloat16(b);
    unsigned short ua = *(unsigned short*)&ha, ub = *(unsigned short*)&hb;
    return (uint32_t)ua | ((uint32_t)ub << 16);
}

__global__ void conv_x_kernel(const float* __restrict__ x,
                              uint32_t* __restrict__ xhi,
                              uint32_t* __restrict__ xlo, int nwords) {
    int i = blockIdx.x * blockDim.x + threadIdx.x;
    if (i >= nwords) return;
    float2 v = ((const float2*)x)[i];
    __nv_bfloat16 h0 = __float2bfloat16(v.x), h1b = __float2bfloat16(v.y);
    float l0 = v.x - __bfloat162float(h0);
    float l1 = v.y - __bfloat162float(h1b);
    unsigned short u0 = *(unsigned short*)&h0, u1 = *(unsigned short*)&h1b;
    xhi[i] = (uint32_t)u0 | ((uint32_t)u1 << 16);
    xlo[i] = pack_bf2(l0, l1);
}

// W1[128,128] -> B^T images: Bt[n][kpair] (n-major, WSTR-padded), hi/lo
__global__ void prep_w_kernel(const float* __restrict__ W,
                              uint32_t* __restrict__ whi,
                              uint32_t* __restrict__ wlo) {
    int i = blockIdx.x * blockDim.x + threadIdx.x;
    if (i >= 128 * 64) return;
    int nrow = i >> 6, kp = i & 63;
    float v0 = W[(2 * kp) * 128 + nrow];
    float v1 = W[(2 * kp + 1) * 128 + nrow];
    __nv_bfloat16 h0 = __float2bfloat16(v0), h1b = __float2bfloat16(v1);
    float l0 = v0 - __bfloat162float(h0);
    float l1 = v1 - __bfloat162float(h1b);
    unsigned short u0 = *(unsigned short*)&h0, u1 = *(unsigned short*)&h1b;
    whi[nrow * WSTR + kp] = (uint32_t)u0 | ((uint32_t)u1 << 16);
    wlo[nrow * WSTR + kp] = pack_bf2(l0, l1);
}

// ---------------------------------------------------------------------------
// Layer-1 GEMM via mma.sync bf16 (hi/lo split) + fused logits1.
// CTA = 256 threads (8 warps), tile 128 nodes x 128 cols, K = 128.
// Warp w computes rows [base + w*16, +16). m16n8k16 fragments.
// ---------------------------------------------------------------------------
__device__ __forceinline__ void mma_bf16(float& c0, float& c1, float& c2, float& c3,
                                         uint32_t a0, uint32_t a1, uint32_t a2, uint32_t a3,
                                         uint32_t b0, uint32_t b1) {
    asm volatile(
        "mma.sync.aligned.m16n8k16.row.col.f32.bf16.bf16.f32 "
        "{%0,%1,%2,%3}, {%4,%5,%6,%7}, {%8,%9}, {%0,%1,%2,%3};"
        : "+f"(c0), "+f"(c1), "+f"(c2), "+f"(c3)
        : "r"(a0), "r"(a1), "r"(a2), "r"(a3), "r"(b0), "r"(b1));
}

#define SMW_WORDS (128 * WSTR)

__global__ void __launch_bounds__(256)
gemm1_mma_kernel(const uint32_t* __restrict__ xhi,
                 const uint32_t* __restrict__ xlo,
                 const uint32_t* __restrict__ whi,
                 const uint32_t* __restrict__ wlo,
                 const float* __restrict__ a_src,
                 const float* __restrict__ a_dst,
                 float* __restrict__ h1,
                 float* __restrict__ es, float* __restrict__ ed, int n) {
    extern __shared__ uint32_t smem_u[];
    uint32_t* sWhi = smem_u;                    // [128][WSTR]
    uint32_t* sWlo = smem_u + SMW_WORDS;
    float* sAs = (float*)(smem_u + 2 * SMW_WORDS);
    float* sAd = sAs + 128;

    const int tid = threadIdx.x;
    const int w = tid >> 5, lane = tid & 31;
    const int g = lane >> 2, t2 = lane & 3;

    for (int i = tid; i < SMW_WORDS; i += 256) {
        sWhi[i] = whi[i];
        sWlo[i] = wlo[i];
    }
    if (tid < 128) { sAs[tid] = a_src[tid]; sAd[tid] = a_dst[tid]; }
    __syncthreads();

    const int base = blockIdx.x * 128 + w * 16;
    const int r0 = base + g, r1 = base + g + 8;
    const uint32_t* x0h = xhi + (size_t)r0 * 64;
    const uint32_t* x1h = xhi + (size_t)r1 * 64;
    const uint32_t* x0l = xlo + (size_t)r0 * 64;
    const uint32_t* x1l = xlo + (size_t)r1 * 64;

    float acc[16][4];
    #pragma unroll
    for (int nt = 0; nt < 16; nt++)
        #pragma unroll
        for (int j = 0; j < 4; j++) acc[nt][j] = 0.f;

    #pragma unroll
    for (int ks = 0; ks < 8; ks++) {
        const int ko = ks * 8 + t2;
        uint32_t ah0 = x0h[ko],     ah1 = x1h[ko];
        uint32_t ah2 = x0h[ko + 4], ah3 = x1h[ko + 4];
        uint32_t al0 = x0l[ko],     al1 = x1l[ko];
        uint32_t al2 = x0l[ko + 4], al3 = x1l[ko + 4];
        #pragma unroll
        for (int nt = 0; nt < 16; nt++) {
            const int bidx = (nt * 8 + g) * WSTR + ks * 8 + t2;
            uint32_t bh0 = sWhi[bidx], bh1 = sWhi[bidx + 4];
            uint32_t bl0 = sWlo[bidx], bl1 = sWlo[bidx + 4];
            mma_bf16(acc[nt][0], acc[nt][1], acc[nt][2], acc[nt][3],
                     ah0, ah1, ah2, ah3, bh0, bh1);
            mma_bf16(acc[nt][0], acc[nt][1], acc[nt][2], acc[nt][3],
                     ah0, ah1, ah2, ah3, bl0, bl1);
            mma_bf16(acc[nt][0], acc[nt][1], acc[nt][2], acc[nt][3],
                     al0, al1, al2, al3, bh0, bh1);
        }
    }

    // Epilogue: write h1 rows + fused logits (per-head dot with a_src/a_dst)
    float ss0[4] = {0.f, 0.f, 0.f, 0.f}, dd0[4] = {0.f, 0.f, 0.f, 0.f};
    float ss1[4] = {0.f, 0.f, 0.f, 0.f}, dd1[4] = {0.f, 0.f, 0.f, 0.f};
    #pragma unroll
    for (int nt = 0; nt < 16; nt++) {
        const int c = nt * 8 + t2 * 2;
        const int head = nt >> 2;
        float as0 = sAs[c], as1 = sAs[c + 1];
        float ad0 = sAd[c], ad1 = sAd[c + 1];
        ss0[head] += acc[nt][0] * as0 + acc[nt][1] * as1;
        dd0[head] += acc[nt][0] * ad0 + acc[nt][1] * ad1;
        ss1[head] += acc[nt][2] * as0 + acc[nt][3] * as1;
        dd1[head] += acc[nt][2] * ad0 + acc[nt][3] * ad1;
        if (r0 < n) *(float2*)&h1[(size_t)r0 * 128 + c] = make_float2(acc[nt][0], acc[nt][1]);
        if (r1 < n) *(float2*)&h1[(size_t)r1 * 128 + c] = make_float2(acc[nt][2], acc[nt][3]);
    }
    #pragma unroll
    for (int h = 0; h < 4; h++) {
        ss0[h] += __shfl_xor_sync(0xFFFFFFFF, ss0[h], 1);
        ss0[h] += __shfl_xor_sync(0xFFFFFFFF, ss0[h], 2);
        dd0[h] += __shfl_xor_sync(0xFFFFFFFF, dd0[h], 1);
        dd0[h] += __shfl_xor_sync(0xFFFFFFFF, dd0[h], 2);
        ss1[h] += __shfl_xor_sync(0xFFFFFFFF, ss1[h], 1);
        ss1[h] += __shfl_xor_sync(0xFFFFFFFF, ss1[h], 2);
        dd1[h] += __shfl_xor_sync(0xFFFFFFFF, dd1[h], 1);
        dd1[h] += __shfl_xor_sync(0xFFFFFFFF, dd1[h], 2);
    }
    if (t2 == 0) {
        if (r0 < n) {
            #pragma unroll
            for (int h = 0; h < 4; h++) {
                es[r0 * 4 + h] = ss0[h];
                ed[r0 * 4 + h] = dd0[h];
            }
        }
        if (r1 < n) {
            #pragma unroll
            for (int h = 0; h < 4; h++) {
                es[r1 * 4 + h] = ss1[h];
                ed[r1 * 4 + h] = dd1[h];
            }
        }
    }
}

// ---------------------------------------------------------------------------
// FFMA GEMM for layer 2 (small): H[n,32] = X[n,128] @ W[128,32]
// ---------------------------------------------------------------------------
__global__ void gemm2_kernel(const float* __restrict__ X,
                             const float* __restrict__ W,
                             float* __restrict__ Hout, int n) {
    constexpr int OUT_COLS = 32, K = 128, KC = 32;
    constexpr int COL_T = 8, NPT = 4, TILE_N = 128;
    __shared__ __align__(16) float sW[KC][OUT_COLS];
    __shared__ float sX[TILE_N][KC + 1];
    const int tid = threadIdx.x;
    const int col_t = tid % COL_T, row_t = tid / COL_T;

    int base = blockIdx.x * TILE_N;
    float4 acc[NPT];
    #pragma unroll
    for (int j = 0; j < NPT; j++) acc[j] = make_float4(0.f, 0.f, 0.f, 0.f);
    for (int kc = 0; kc < K; kc += KC) {
        for (int i = tid; i < KC * OUT_COLS; i += 256) {
            int kk = i / OUT_COLS, cc = i % OUT_COLS;
            sW[kk][cc] = W[(kc + kk) * OUT_COLS + cc];
        }
        for (int i = tid; i < TILE_N * KC; i += 256) {
            int r = i / KC, kk = i % KC;
            int node = base + r;
            sX[r][kk] = (node < n) ? X[(size_t)node * K + kc + kk] : 0.f;
        }
        __syncthreads();
        #pragma unroll
        for (int kk = 0; kk < KC; kk++) {
            float4 w = *(const float4*)&sW[kk][col_t * 4];
            #pragma unroll
            for (int j = 0; j < NPT; j++) {
                float xv = sX[row_t * NPT + j][kk];
                acc[j].x += xv * w.x; acc[j].y += xv * w.y;
                acc[j].z += xv * w.z; acc[j].w += xv * w.w;
            }
        }
        __syncthreads();
    }
    #pragma unroll
    for (int j = 0; j < NPT; j++) {
        int node = base + row_t * NPT + j;
        if (node < n)
            *(float4*)&Hout[(size_t)node * OUT_COLS + col_t * 4] = acc[j];
    }
}

__global__ void logits2_kernel(const float* __restrict__ Hm,
                               const float* __restrict__ a_src,
                               const float* __restrict__ a_dst,
                               float* __restrict__ es,
                               float* __restrict__ ed, int n) {
    int node = (blockIdx.x * blockDim.x + threadIdx.x) >> 5;
    if (node >= n) return;
    int lane = threadIdx.x & 31;
    float h = Hm[(size_t)node * OC2 + lane];
    float ss = h * a_src[lane];
    float dd = h * a_dst[lane];
    #pragma unroll
    for (int m = 1; m < 32; m <<= 1) {
        ss += __shfl_xor_sync(0xFFFFFFFF, ss, m);
        dd += __shfl_xor_sync(0xFFFFFFFF, dd, m);
    }
    if (lane == 0) { es[node] = ss; ed[node] = dd; }
}

// ---------------------------------------------------------------------------
// Fused aggregations (warp per dst, CSR, shuffle-broadcast indices)
// ---------------------------------------------------------------------------
__global__ void agg1_kernel(const int* __restrict__ rowptr,
                            const int* __restrict__ csr_src,
                            const float* __restrict__ Hm,
                            const float* __restrict__ es,
                            const float* __restrict__ ed,
                            const float* __restrict__ bias,
                            float* __restrict__ out, int n) {
    int d = (blockIdx.x * blockDim.x + threadIdx.x) >> 5;
    if (d >= n) return;
    int lane = threadIdx.x & 31;
    int head = lane >> 3;
    float edv = ed[d * H1 + head];
    float a0 = 0.f, a1 = 0.f, a2 = 0.f, a3 = 0.f, den = 0.f;
    int beg = rowptr[d], end = rowptr[d + 1];
    for (int base = beg; base < end; base += 32) {
        int e = base + lane;
        int sidx = (e < end) ? csr_src[e] : 0;
        int cnt = end - base; if (cnt > 32) cnt = 32;
        #pragma unroll 4
        for (int j = 0; j < cnt; j++) {
            int s = __shfl_sync(0xFFFFFFFF, sidx, j);
            float v = es[s * H1 + head] + edv;
            v = v > 0.f ? v : 0.2f * v;
            float ex = __expf(v);
            den += ex;
            float4 hv = *(const float4*)&Hm[(size_t)s * F1 + lane * 4];
            a0 += hv.x * ex; a1 += hv.y * ex; a2 += hv.z * ex; a3 += hv.w * ex;
        }
    }
    float inv = 1.0f / den;
    float4 bv = *(const float4*)&bias[lane * 4];
    float r0 = a0 * inv + bv.x;
    float r1 = a1 * inv + bv.y;
    float r2 = a2 * inv + bv.z;
    float r3 = a3 * inv + bv.w;
    r0 = r0 > 0.f ? r0 : expm1f(r0);
    r1 = r1 > 0.f ? r1 : expm1f(r1);
    r2 = r2 > 0.f ? r2 : expm1f(r2);
    r3 = r3 > 0.f ? r3 : expm1f(r3);
    *(float4*)&out[(size_t)d * F1 + lane * 4] = make_float4(r0, r1, r2, r3);
}

__global__ void agg2_kernel(const int* __restrict__ rowptr,
                            const int* __restrict__ csr_src,
                            const float* __restrict__ Hm,
                            const float* __restrict__ es,
                            const float* __restrict__ ed,
                            const float* __restrict__ bias,
                            float* __restrict__ out, int n) {
    int d = (blockIdx.x * blockDim.x + threadIdx.x) >> 5;
    if (d >= n) return;
    int lane = threadIdx.x & 31;
    float edv = ed[d];
    float acc = 0.f, den = 0.f;
    int beg = rowptr[d], end = rowptr[d + 1];
    for (int base = beg; base < end; base += 32) {
        int e = base + lane;
        int sidx = (e < end) ? csr_src[e] : 0;
        int cnt = end - base; if (cnt > 32) cnt = 32;
        #pragma unroll 4
        for (int j = 0; j < cnt; j++) {
            int s = __shfl_sync(0xFFFFFFFF, sidx, j);
            float v = es[s] + edv;
            v = v > 0.f ? v : 0.2f * v;
            float ex = __expf(v);
            den += ex;
            acc += Hm[(size_t)s * OC2 + lane] * ex;
        }
    }
    out[(size_t)d * OC2 + lane] = acc / den + bias[lane];
}

// ---------------------------------------------------------------------------
// Launch
// ---------------------------------------------------------------------------
extern "C" void kernel_launch(void* const* d_in, const int* in_sizes, int n_in,
                              void* d_out, int out_size) {
    const float* x      = (const float*)d_in[0];
    const int*   ei     = (const int*)  d_in[1];
    const float* W1     = (const float*)d_in[2];
    const float* a_src1 = (const float*)d_in[3];
    const float* a_dst1 = (const float*)d_in[4];
    const float* b1     = (const float*)d_in[5];
    const float* W2     = (const float*)d_in[6];
    const float* a_src2 = (const float*)d_in[7];
    const float* a_dst2 = (const float*)d_in[8];
    const float* b2     = (const float*)d_in[9];
    float* out = (float*)d_out;

    int n = in_sizes[0] / 128;
    long long ee = in_sizes[1];
    int E = (int)(ee / 2);
    if (E > EMAX) E = (int)(ee / 4);
    int ET = E + n;

    float *h1, *o1, *h2, *es1, *ed1, *es2, *ed2;
    uint32_t *xhi, *xlo, *whi, *wlo;
    int *deg, *rowptr, *cursor, *csr;
    cudaGetSymbolAddress((void**)&h1,  g_h1);
    cudaGetSymbolAddress((void**)&o1,  g_o1);
    cudaGetSymbolAddress((void**)&h2,  g_h2);
    cudaGetSymbolAddress((void**)&es1, g_es1);
    cudaGetSymbolAddress((void**)&ed1, g_ed1);
    cudaGetSymbolAddress((void**)&es2, g_es2);
    cudaGetSymbolAddress((void**)&ed2, g_ed2);
    cudaGetSymbolAddress((void**)&xhi, g_xhi);
    cudaGetSymbolAddress((void**)&xlo, g_xlo);
    cudaGetSymbolAddress((void**)&whi, g_whi);
    cudaGetSymbolAddress((void**)&wlo, g_wlo);
    cudaGetSymbolAddress((void**)&deg, g_deg);
    cudaGetSymbolAddress((void**)&rowptr, g_rowptr);
    cudaGetSymbolAddress((void**)&cursor, g_cursor);
    cudaGetSymbolAddress((void**)&csr, g_csr_src);

    const int smw_bytes = 2 * SMW_WORDS * 4 + 256 * 4;
    cudaFuncSetAttribute(gemm1_mma_kernel,
                         cudaFuncAttributeMaxDynamicSharedMemorySize, smw_bytes);

    // -------- preprocessing --------
    cudaMemsetAsync(deg, 0, (size_t)n * sizeof(int));
    conv_x_kernel<<<cdiv(n * 64, 256), 256>>>(x, xhi, xlo, n * 64);
    prep_w_kernel<<<32, 256>>>(W1, whi, wlo);
    deg_kernel<<<cdiv(ET, 256), 256>>>(ei, E, n, deg);
    scan_kernel<<<1, 1024>>>(deg, rowptr, cursor, n);
    scatter_kernel<<<cdiv(ET, 256), 256>>>(ei, E, n, cursor, csr);

    // -------- layer 1 --------
    gemm1_mma_kernel<<<cdiv(n, 128), 256, smw_bytes>>>(
        xhi, xlo, whi, wlo, a_src1, a_dst1, h1, es1, ed1, n);
    agg1_kernel<<<cdiv(n * 32, 256), 256>>>(rowptr, csr, h1, es1, ed1, b1, o1, n);

    // -------- layer 2 --------
    gemm2_kernel<<<cdiv(n, 128), 256>>>(o1, W2, h2, n);
    logits2_kernel<<<cdiv(n * 32, 256), 256>>>(h2, a_src2, a_dst2, es2, ed2, n);
    agg2_kernel<<<cdiv(n * 32, 256), 256>>>(rowptr, csr, h2, es2, ed2, b2, out, n);
}

// round 7
// speedup vs baseline: 1.6119x; 1.6119x over previous
#include <cuda_runtime.h>
#include <cuda_bf16.h>
#include <math.h>
#include <stdint.h>

// ---------------------------------------------------------------------------
// Problem constants
// ---------------------------------------------------------------------------
#define NMAX   50176            // padded (50000 real)
#define EMAX   800000
#define ETMAX  (NMAX + EMAX)
#define F1     128
#define H1     4
#define OC2    32
#define WSTR   68               // padded uint32 row stride for B tiles in SMEM
#define SCAN_B 1024

// ---------------------------------------------------------------------------
// Scratch (device globals)
// ---------------------------------------------------------------------------
__device__ __align__(16) float    g_h1 [NMAX * F1];
__device__ __align__(16) float    g_o1 [NMAX * F1];
__device__ __align__(16) float    g_h2 [NMAX * OC2];
__device__ __align__(16) float    g_es1[NMAX * H1];
__device__ __align__(16) float    g_ed1[NMAX * H1];
__device__ __align__(16) float    g_es2[NMAX];
__device__ __align__(16) float    g_ed2[NMAX];
__device__ __align__(16) uint32_t g_w1hi[128 * WSTR]; // W1^T hi, n-major padded
__device__ __align__(16) uint32_t g_w1lo[128 * WSTR];
__device__ __align__(16) uint32_t g_w2hi[32 * WSTR];  // W2^T hi
__device__ __align__(16) uint32_t g_w2lo[32 * WSTR];
__device__ int g_deg[NMAX];
__device__ int g_rowptr[NMAX + 1];
__device__ int g_cursor[NMAX];
__device__ int g_csr_src[ETMAX];
__device__ int g_bsum[64];
__device__ int g_boff[64];

static inline int cdiv(int a, int b) { return (a + b - 1) / b; }

// ---------------------------------------------------------------------------
// Preprocessing
// ---------------------------------------------------------------------------
__device__ __forceinline__ int block_detect_i64(const int* ei) {
    int any = 0;
    #pragma unroll 8
    for (int k = 1; k < 128; k += 2) any |= ei[k];
    return (any == 0) ? 1 : 0;
}

__global__ void deg_kernel(const int* __restrict__ ei, int E, int n,
                           int* __restrict__ deg) {
    __shared__ int s64;
    if (threadIdx.x == 0) s64 = block_detect_i64(ei);
    __syncthreads();
    int i = blockIdx.x * blockDim.x + threadIdx.x;
    if (i >= E + n) return;
    int d;
    if (i < E) {
        d = s64 ? (int)((const long long*)ei)[(long long)E + i] : ei[E + i];
    } else {
        d = i - E;
    }
    atomicAdd(&deg[d], 1);
}

// Multi-block scan (proven fast path): block inclusive scans + partials + fix
__global__ void scan_block_kernel(const int* __restrict__ deg,
                                  int* __restrict__ rowptr,
                                  int* __restrict__ bsum, int n) {
    __shared__ int sh[SCAN_B];
    int i = blockIdx.x * SCAN_B + threadIdx.x;
    int v = (i < n) ? deg[i] : 0;
    sh[threadIdx.x] = v;
    __syncthreads();
    for (int off = 1; off < SCAN_B; off <<= 1) {
        int t = (threadIdx.x >= off) ? sh[threadIdx.x - off] : 0;
        __syncthreads();
        sh[threadIdx.x] += t;
        __syncthreads();
    }
    if (i < n) rowptr[i + 1] = sh[threadIdx.x];   // inclusive, pre-offset
    if (threadIdx.x == SCAN_B - 1) bsum[blockIdx.x] = sh[SCAN_B - 1];
}

__global__ void scan_partials_kernel(const int* __restrict__ bsum,
                                     int* __restrict__ boff, int nb) {
    if (threadIdx.x == 0 && blockIdx.x == 0) {
        int run = 0;
        for (int b = 0; b < nb; b++) { boff[b] = run; run += bsum[b]; }
    }
}

__global__ void finalize_rowptr_kernel(int* __restrict__ rowptr,
                                       int* __restrict__ cursor,
                                       const int* __restrict__ boff, int n) {
    int idx = blockIdx.x * blockDim.x + threadIdx.x;
    if (idx > n) return;
    int v;
    if (idx == 0) v = 0;
    else          v = rowptr[idx] + boff[(idx - 1) / SCAN_B];
    rowptr[idx] = v;
    if (idx < n) cursor[idx] = v;
}

__global__ void scatter_kernel(const int* __restrict__ ei, int E, int n,
                               int* __restrict__ cursor,
                               int* __restrict__ csr_src) {
    __shared__ int s64;
    if (threadIdx.x == 0) s64 = block_detect_i64(ei);
    __syncthreads();
    int i = blockIdx.x * blockDim.x + threadIdx.x;
    if (i >= E + n) return;
    int s, d;
    if (i < E) {
        if (s64) {
            const long long* p = (const long long*)ei;
            s = (int)p[i];
            d = (int)p[(long long)E + i];
        } else {
            s = ei[i];
            d = ei[E + i];
        }
    } else {
        s = i - E;
        d = i - E;
    }
    int p = atomicAdd(&cursor[d], 1);
    csr_src[p] = s;
}

// ---------------------------------------------------------------------------
// bf16 hi/lo pack helpers
// ---------------------------------------------------------------------------
__device__ __forceinline__ uint32_t pack_bf2(float a, float b) {
    __nv_bfloat16 ha = __float2bfloat16(a), hb = __float2bfloat16(b);
    unsigned short ua = *(unsigned short*)&ha, ub = *(unsigned short*)&hb;
    return (uint32_t)ua | ((uint32_t)ub << 16);
}
__device__ __forceinline__ void split2(float2 v, uint32_t& hi, uint32_t& lo) {
    __nv_bfloat16 h0 = __float2bfloat16(v.x), h1b = __float2bfloat16(v.y);
    unsigned short u0 = *(unsigned short*)&h0, u1 = *(unsigned short*)&h1b;
    hi = (uint32_t)u0 | ((uint32_t)u1 << 16);
    lo = pack_bf2(v.x - __bfloat162float(h0), v.y - __bfloat162float(h1b));
}

// W1[128,128] and W2[128,32] -> B^T images (n-major, WSTR-padded), hi/lo
__global__ void prep_w_kernel(const float* __restrict__ W1,
                              const float* __restrict__ W2,
                              uint32_t* __restrict__ w1hi, uint32_t* __restrict__ w1lo,
                              uint32_t* __restrict__ w2hi, uint32_t* __restrict__ w2lo) {
    int i = blockIdx.x * blockDim.x + threadIdx.x;
    if (i < 128 * 64) {
        int nrow = i >> 6, kp = i & 63;
        float2 v = make_float2(W1[(2 * kp) * 128 + nrow], W1[(2 * kp + 1) * 128 + nrow]);
        uint32_t hi, lo; split2(v, hi, lo);
        w1hi[nrow * WSTR + kp] = hi;
        w1lo[nrow * WSTR + kp] = lo;
    } else if (i < 128 * 64 + 32 * 64) {
        int j = i - 128 * 64;
        int nrow = j >> 6, kp = j & 63;
        float2 v = make_float2(W2[(2 * kp) * 32 + nrow], W2[(2 * kp + 1) * 32 + nrow]);
        uint32_t hi, lo; split2(v, hi, lo);
        w2hi[nrow * WSTR + kp] = hi;
        w2lo[nrow * WSTR + kp] = lo;
    }
}

// ---------------------------------------------------------------------------
// Unified GEMM via mma.sync bf16 hi/lo split + fused attention logits.
// H[n, NCOLS] = X[n,128] @ W[128, NCOLS];  es/ed[n, HEADS] fused.
// CTA = 256 threads (8 warps); warp computes 16 rows x NCOLS.
// 32 cols per head in both layers -> head = nt >> 2.
// ---------------------------------------------------------------------------
__device__ __forceinline__ void mma_bf16(float& c0, float& c1, float& c2, float& c3,
                                         uint32_t a0, uint32_t a1, uint32_t a2, uint32_t a3,
                                         uint32_t b0, uint32_t b1) {
    asm volatile(
        "mma.sync.aligned.m16n8k16.row.col.f32.bf16.bf16.f32 "
        "{%0,%1,%2,%3}, {%4,%5,%6,%7}, {%8,%9}, {%0,%1,%2,%3};"
        : "+f"(c0), "+f"(c1), "+f"(c2), "+f"(c3)
        : "r"(a0), "r"(a1), "r"(a2), "r"(a3), "r"(b0), "r"(b1));
}

template<int NCOLS, int HEADS>
__global__ void __launch_bounds__(256)
gemm_mma_kernel(const float* __restrict__ X,
                const uint32_t* __restrict__ whi,
                const uint32_t* __restrict__ wlo,
                const float* __restrict__ a_src,
                const float* __restrict__ a_dst,
                float* __restrict__ Hout,
                float* __restrict__ es, float* __restrict__ ed, int n) {
    constexpr int NT = NCOLS / 8;
    constexpr int WWORDS = NCOLS * WSTR;
    extern __shared__ uint32_t smem_u[];
    uint32_t* sWhi = smem_u;
    uint32_t* sWlo = smem_u + WWORDS;
    float* sAs = (float*)(smem_u + 2 * WWORDS);
    float* sAd = sAs + NCOLS;

    const int tid = threadIdx.x;
    const int w = tid >> 5, lane = tid & 31;
    const int g = lane >> 2, t2 = lane & 3;

    for (int i = tid; i < WWORDS; i += 256) {
        sWhi[i] = whi[i];
        sWlo[i] = wlo[i];
    }
    if (tid < NCOLS) { sAs[tid] = a_src[tid]; sAd[tid] = a_dst[tid]; }
    __syncthreads();

    const int base = blockIdx.x * 128 + w * 16;
    const int r0 = base + g, r1 = base + g + 8;
    const bool v0 = r0 < n, v1 = r1 < n;
    const float* x0 = X + (size_t)r0 * 128;
    const float* x1 = X + (size_t)r1 * 128;

    float acc[NT][4];
    #pragma unroll
    for (int nt = 0; nt < NT; nt++)
        #pragma unroll
        for (int j = 0; j < 4; j++) acc[nt][j] = 0.f;

    #pragma unroll
    for (int ks = 0; ks < 8; ks++) {
        const int co = (ks * 8 + t2) * 2;     // fp32 column offset
        float2 f00 = v0 ? *(const float2*)&x0[co]     : make_float2(0.f, 0.f);
        float2 f02 = v0 ? *(const float2*)&x0[co + 8] : make_float2(0.f, 0.f);
        float2 f10 = v1 ? *(const float2*)&x1[co]     : make_float2(0.f, 0.f);
        float2 f12 = v1 ? *(const float2*)&x1[co + 8] : make_float2(0.f, 0.f);
        uint32_t ah0, al0, ah1, al1, ah2, al2, ah3, al3;
        split2(f00, ah0, al0);
        split2(f10, ah1, al1);
        split2(f02, ah2, al2);
        split2(f12, ah3, al3);
        #pragma unroll
        for (int nt = 0; nt < NT; nt++) {
            const int bidx = (nt * 8 + g) * WSTR + ks * 8 + t2;
            uint32_t bh0 = sWhi[bidx], bh1 = sWhi[bidx + 4];
            uint32_t bl0 = sWlo[bidx], bl1 = sWlo[bidx + 4];
            mma_bf16(acc[nt][0], acc[nt][1], acc[nt][2], acc[nt][3],
                     ah0, ah1, ah2, ah3, bh0, bh1);
            mma_bf16(acc[nt][0], acc[nt][1], acc[nt][2], acc[nt][3],
                     ah0, ah1, ah2, ah3, bl0, bl1);
            mma_bf16(acc[nt][0], acc[nt][1], acc[nt][2], acc[nt][3],
                     al0, al1, al2, al3, bh0, bh1);
        }
    }

    // Epilogue: write H rows + fused per-head logits (shuffle-reduce over t2)
    float ss0[HEADS], dd0[HEADS], ss1[HEADS], dd1[HEADS];
    #pragma unroll
    for (int h = 0; h < HEADS; h++) { ss0[h] = dd0[h] = ss1[h] = dd1[h] = 0.f; }
    #pragma unroll
    for (int nt = 0; nt < NT; nt++) {
        const int c = nt * 8 + t2 * 2;
        const int head = nt >> 2;          // 32 cols per head in both layers
        float as0 = sAs[c], as1 = sAs[c + 1];
        float ad0 = sAd[c], ad1 = sAd[c + 1];
        ss0[head] += acc[nt][0] * as0 + acc[nt][1] * as1;
        dd0[head] += acc[nt][0] * ad0 + acc[nt][1] * ad1;
        ss1[head] += acc[nt][2] * as0 + acc[nt][3] * as1;
        dd1[head] += acc[nt][2] * ad0 + acc[nt][3] * ad1;
        if (v0) *(float2*)&Hout[(size_t)r0 * NCOLS + c] = make_float2(acc[nt][0], acc[nt][1]);
        if (v1) *(float2*)&Hout[(size_t)r1 * NCOLS + c] = make_float2(acc[nt][2], acc[nt][3]);
    }
    #pragma unroll
    for (int h = 0; h < HEADS; h++) {
        ss0[h] += __shfl_xor_sync(0xFFFFFFFF, ss0[h], 1);
        ss0[h] += __shfl_xor_sync(0xFFFFFFFF, ss0[h], 2);
        dd0[h] += __shfl_xor_sync(0xFFFFFFFF, dd0[h], 1);
        dd0[h] += __shfl_xor_sync(0xFFFFFFFF, dd0[h], 2);
        ss1[h] += __shfl_xor_sync(0xFFFFFFFF, ss1[h], 1);
        ss1[h] += __shfl_xor_sync(0xFFFFFFFF, ss1[h], 2);
        dd1[h] += __shfl_xor_sync(0xFFFFFFFF, dd1[h], 1);
        dd1[h] += __shfl_xor_sync(0xFFFFFFFF, dd1[h], 2);
    }
    if (t2 == 0) {
        if (v0) {
            #pragma unroll
            for (int h = 0; h < HEADS; h++) {
                es[r0 * HEADS + h] = ss0[h];
                ed[r0 * HEADS + h] = dd0[h];
            }
        }
        if (v1) {
            #pragma unroll
            for (int h = 0; h < HEADS; h++) {
                es[r1 * HEADS + h] = ss1[h];
                ed[r1 * HEADS + h] = dd1[h];
            }
        }
    }
}

// ---------------------------------------------------------------------------
// Fused aggregations (warp per dst, CSR, shuffle-broadcast indices)
// ---------------------------------------------------------------------------
__global__ void agg1_kernel(const int* __restrict__ rowptr,
                            const int* __restrict__ csr_src,
                            const float* __restrict__ Hm,
                            const float* __restrict__ es,
                            const float* __restrict__ ed,
                            const float* __restrict__ bias,
                            float* __restrict__ out, int n) {
    int d = (blockIdx.x * blockDim.x + threadIdx.x) >> 5;
    if (d >= n) return;
    int lane = threadIdx.x & 31;
    int head = lane >> 3;
    float edv = ed[d * H1 + head];
    float a0 = 0.f, a1 = 0.f, a2 = 0.f, a3 = 0.f, den = 0.f;
    int beg = rowptr[d], end = rowptr[d + 1];
    for (int base = beg; base < end; base += 32) {
        int e = base + lane;
        int sidx = (e < end) ? csr_src[e] : 0;
        int cnt = end - base; if (cnt > 32) cnt = 32;
        #pragma unroll 4
        for (int j = 0; j < cnt; j++) {
            int s = __shfl_sync(0xFFFFFFFF, sidx, j);
            float v = es[s * H1 + head] + edv;
            v = v > 0.f ? v : 0.2f * v;
            float ex = __expf(v);
            den += ex;
            float4 hv = *(const float4*)&Hm[(size_t)s * F1 + lane * 4];
            a0 += hv.x * ex; a1 += hv.y * ex; a2 += hv.z * ex; a3 += hv.w * ex;
        }
    }
    float inv = 1.0f / den;
    float4 bv = *(const float4*)&bias[lane * 4];
    float r0 = a0 * inv + bv.x;
    float r1 = a1 * inv + bv.y;
    float r2 = a2 * inv + bv.z;
    float r3 = a3 * inv + bv.w;
    r0 = r0 > 0.f ? r0 : expm1f(r0);
    r1 = r1 > 0.f ? r1 : expm1f(r1);
    r2 = r2 > 0.f ? r2 : expm1f(r2);
    r3 = r3 > 0.f ? r3 : expm1f(r3);
    *(float4*)&out[(size_t)d * F1 + lane * 4] = make_float4(r0, r1, r2, r3);
}

__global__ void agg2_kernel(const int* __restrict__ rowptr,
                            const int* __restrict__ csr_src,
                            const float* __restrict__ Hm,
                            const float* __restrict__ es,
                            const float* __restrict__ ed,
                            const float* __restrict__ bias,
                            float* __restrict__ out, int n) {
    int d = (blockIdx.x * blockDim.x + threadIdx.x) >> 5;
    if (d >= n) return;
    int lane = threadIdx.x & 31;
    float edv = ed[d];
    float acc = 0.f, den = 0.f;
    int beg = rowptr[d], end = rowptr[d + 1];
    for (int base = beg; base < end; base += 32) {
        int e = base + lane;
        int sidx = (e < end) ? csr_src[e] : 0;
        int cnt = end - base; if (cnt > 32) cnt = 32;
        #pragma unroll 4
        for (int j = 0; j < cnt; j++) {
            int s = __shfl_sync(0xFFFFFFFF, sidx, j);
            float v = es[s] + edv;
            v = v > 0.f ? v : 0.2f * v;
            float ex = __expf(v);
            den += ex;
            acc += Hm[(size_t)s * OC2 + lane] * ex;
        }
    }
    out[(size_t)d * OC2 + lane] = acc / den + bias[lane];
}

// ---------------------------------------------------------------------------
// Launch
// ---------------------------------------------------------------------------
extern "C" void kernel_launch(void* const* d_in, const int* in_sizes, int n_in,
                              void* d_out, int out_size) {
    const float* x      = (const float*)d_in[0];
    const int*   ei     = (const int*)  d_in[1];
    const float* W1     = (const float*)d_in[2];
    const float* a_src1 = (const float*)d_in[3];
    const float* a_dst1 = (const float*)d_in[4];
    const float* b1     = (const float*)d_in[5];
    const float* W2     = (const float*)d_in[6];
    const float* a_src2 = (const float*)d_in[7];
    const float* a_dst2 = (const float*)d_in[8];
    const float* b2     = (const float*)d_in[9];
    float* out = (float*)d_out;

    int n = in_sizes[0] / 128;
    long long ee = in_sizes[1];
    int E = (int)(ee / 2);
    if (E > EMAX) E = (int)(ee / 4);
    int ET = E + n;
    int nblk = cdiv(n, SCAN_B);

    float *h1, *o1, *h2, *es1, *ed1, *es2, *ed2;
    uint32_t *w1hi, *w1lo, *w2hi, *w2lo;
    int *deg, *rowptr, *cursor, *csr, *bsum, *boff;
    cudaGetSymbolAddress((void**)&h1,  g_h1);
    cudaGetSymbolAddress((void**)&o1,  g_o1);
    cudaGetSymbolAddress((void**)&h2,  g_h2);
    cudaGetSymbolAddress((void**)&es1, g_es1);
    cudaGetSymbolAddress((void**)&ed1, g_ed1);
    cudaGetSymbolAddress((void**)&es2, g_es2);
    cudaGetSymbolAddress((void**)&ed2, g_ed2);
    cudaGetSymbolAddress((void**)&w1hi, g_w1hi);
    cudaGetSymbolAddress((void**)&w1lo, g_w1lo);
    cudaGetSymbolAddress((void**)&w2hi, g_w2hi);
    cudaGetSymbolAddress((void**)&w2lo, g_w2lo);
    cudaGetSymbolAddress((void**)&deg, g_deg);
    cudaGetSymbolAddress((void**)&rowptr, g_rowptr);
    cudaGetSymbolAddress((void**)&cursor, g_cursor);
    cudaGetSymbolAddress((void**)&csr, g_csr_src);
    cudaGetSymbolAddress((void**)&bsum, g_bsum);
    cudaGetSymbolAddress((void**)&boff, g_boff);

    const int sm1 = (2 * 128 * WSTR + 2 * 128) * 4;
    const int sm2 = (2 * 32 * WSTR + 2 * 32) * 4;
    cudaFuncSetAttribute(gemm_mma_kernel<128, 4>,
                         cudaFuncAttributeMaxDynamicSharedMemorySize, sm1);
    cudaFuncSetAttribute(gemm_mma_kernel<32, 1>,
                         cudaFuncAttributeMaxDynamicSharedMemorySize, sm2);

    // -------- preprocessing --------
    cudaMemsetAsync(deg, 0, (size_t)n * sizeof(int));
    prep_w_kernel<<<cdiv(128 * 64 + 32 * 64, 256), 256>>>(W1, W2, w1hi, w1lo, w2hi, w2lo);
    deg_kernel<<<cdiv(ET, 256), 256>>>(ei, E, n, deg);
    scan_block_kernel<<<nblk, SCAN_B>>>(deg, rowptr, bsum, n);
    scan_partials_kernel<<<1, 32>>>(bsum, boff, nblk);
    finalize_rowptr_kernel<<<cdiv(n + 1, 256), 256>>>(rowptr, cursor, boff, n);
    scatter_kernel<<<cdiv(ET, 256), 256>>>(ei, E, n, cursor, csr);

    // -------- layer 1 --------
    gemm_mma_kernel<128, 4><<<cdiv(n, 128), 256, sm1>>>(
        x, w1hi, w1lo, a_src1, a_dst1, h1, es1, ed1, n);
    agg1_kernel<<<cdiv(n * 32, 256), 256>>>(rowptr, csr, h1, es1, ed1, b1, o1, n);

    // -------- layer 2 --------
    gemm_mma_kernel<32, 1><<<cdiv(n, 128), 256, sm2>>>(
        o1, w2hi, w2lo, a_src2, a_dst2, h2, es2, ed2, n);
    agg2_kernel<<<cdiv(n * 32, 256), 256>>>(rowptr, csr, h2, es2, ed2, b2, out, n);
}

// round 8
// speedup vs baseline: 1.7883x; 1.1095x over previous
#include <cuda_runtime.h>
#include <cuda_bf16.h>
#include <cuda_fp16.h>
#include <math.h>
#include <stdint.h>

// ---------------------------------------------------------------------------
// Problem constants
// ---------------------------------------------------------------------------
#define NMAX   50176            // padded (50000 real)
#define EMAX   800000
#define ETMAX  (NMAX + EMAX)
#define F1     128
#define H1     4
#define OC2    32
#define WSTR   68               // padded uint32 row stride for B tiles in SMEM
#define SCAN_B 1024

// ---------------------------------------------------------------------------
// Scratch (device globals)
// ---------------------------------------------------------------------------
__device__ __align__(16) uint32_t g_h1 [NMAX * 64];   // h1 as half2-packed (128 cols)
__device__ __align__(16) float    g_o1 [NMAX * F1];   // layer1 out (fp32, feeds gemm2)
__device__ __align__(16) uint32_t g_h2 [NMAX * 16];   // h2 as half2-packed (32 cols)
__device__ __align__(16) float    g_es1[NMAX * H1];
__device__ __align__(16) float    g_ed1[NMAX * H1];
__device__ __align__(16) float    g_es2[NMAX];
__device__ __align__(16) float    g_ed2[NMAX];
__device__ __align__(16) uint32_t g_w1hi[128 * WSTR]; // W1^T hi, n-major padded
__device__ __align__(16) uint32_t g_w1lo[128 * WSTR];
__device__ __align__(16) uint32_t g_w2hi[32 * WSTR];  // W2^T hi
__device__ __align__(16) uint32_t g_w2lo[32 * WSTR];
__device__ int g_deg[NMAX];
__device__ int g_rowptr[NMAX + 1];
__device__ int g_cursor[NMAX];
__device__ int g_csr_src[ETMAX];
__device__ int g_bsum[64];

static inline int cdiv(int a, int b) { return (a + b - 1) / b; }

// ---------------------------------------------------------------------------
// bf16 hi/lo pack helpers
// ---------------------------------------------------------------------------
__device__ __forceinline__ uint32_t pack_bf2(float a, float b) {
    __nv_bfloat16 ha = __float2bfloat16(a), hb = __float2bfloat16(b);
    unsigned short ua = *(unsigned short*)&ha, ub = *(unsigned short*)&hb;
    return (uint32_t)ua | ((uint32_t)ub << 16);
}
__device__ __forceinline__ void split2(float2 v, uint32_t& hi, uint32_t& lo) {
    __nv_bfloat16 h0 = __float2bfloat16(v.x), h1b = __float2bfloat16(v.y);
    unsigned short u0 = *(unsigned short*)&h0, u1 = *(unsigned short*)&h1b;
    hi = (uint32_t)u0 | ((uint32_t)u1 << 16);
    lo = pack_bf2(v.x - __bfloat162float(h0), v.y - __bfloat162float(h1b));
}

// ---------------------------------------------------------------------------
// Preprocessing
// ---------------------------------------------------------------------------
__device__ __forceinline__ int block_detect_i64(const int* ei) {
    int any = 0;
    #pragma unroll 8
    for (int k = 1; k < 128; k += 2) any |= ei[k];
    return (any == 0) ? 1 : 0;
}

// W prep + deg zeroing fused (saves a memset launch)
__global__ void prep_w_kernel(const float* __restrict__ W1,
                              const float* __restrict__ W2,
                              uint32_t* __restrict__ w1hi, uint32_t* __restrict__ w1lo,
                              uint32_t* __restrict__ w2hi, uint32_t* __restrict__ w2lo,
                              int* __restrict__ deg, int n) {
    int i = blockIdx.x * blockDim.x + threadIdx.x;
    if (i < n) deg[i] = 0;
    if (i < 128 * 64) {
        int nrow = i >> 6, kp = i & 63;
        float2 v = make_float2(W1[(2 * kp) * 128 + nrow], W1[(2 * kp + 1) * 128 + nrow]);
        uint32_t hi, lo; split2(v, hi, lo);
        w1hi[nrow * WSTR + kp] = hi;
        w1lo[nrow * WSTR + kp] = lo;
    } else if (i < 128 * 64 + 32 * 64) {
        int j = i - 128 * 64;
        int nrow = j >> 6, kp = j & 63;
        float2 v = make_float2(W2[(2 * kp) * 32 + nrow], W2[(2 * kp + 1) * 32 + nrow]);
        uint32_t hi, lo; split2(v, hi, lo);
        w2hi[nrow * WSTR + kp] = hi;
        w2lo[nrow * WSTR + kp] = lo;
    }
}

__global__ void deg_kernel(const int* __restrict__ ei, int E, int n,
                           int* __restrict__ deg) {
    __shared__ int s64;
    if (threadIdx.x == 0) s64 = block_detect_i64(ei);
    __syncthreads();
    int i = blockIdx.x * blockDim.x + threadIdx.x;
    if (i >= E + n) return;
    int d;
    if (i < E) {
        d = s64 ? (int)((const long long*)ei)[(long long)E + i] : ei[E + i];
    } else {
        d = i - E;
    }
    atomicAdd(&deg[d], 1);
}

__global__ void scan_block_kernel(const int* __restrict__ deg,
                                  int* __restrict__ rowptr,
                                  int* __restrict__ bsum, int n) {
    __shared__ int sh[SCAN_B];
    int i = blockIdx.x * SCAN_B + threadIdx.x;
    int v = (i < n) ? deg[i] : 0;
    sh[threadIdx.x] = v;
    __syncthreads();
    for (int off = 1; off < SCAN_B; off <<= 1) {
        int t = (threadIdx.x >= off) ? sh[threadIdx.x - off] : 0;
        __syncthreads();
        sh[threadIdx.x] += t;
        __syncthreads();
    }
    if (i < n) rowptr[i + 1] = sh[threadIdx.x];   // inclusive, pre-offset
    if (threadIdx.x == SCAN_B - 1) bsum[blockIdx.x] = sh[SCAN_B - 1];
}

// Finalize rowptr with in-block scan of block sums (fused partials pass)
__global__ void finalize_rowptr_kernel(int* __restrict__ rowptr,
                                       int* __restrict__ cursor,
                                       const int* __restrict__ bsum,
                                       int n, int nb) {
    __shared__ int sb[64];
    int t = threadIdx.x;
    if (t < 64) sb[t] = (t < nb) ? bsum[t] : 0;
    __syncthreads();
    #pragma unroll
    for (int off = 1; off < 64; off <<= 1) {
        int v = (t < 64 && t >= off) ? sb[t - off] : 0;
        __syncthreads();
        if (t < 64) sb[t] += v;
        __syncthreads();
    }
    int idx = blockIdx.x * blockDim.x + t;
    if (idx > n) return;
    int v;
    if (idx == 0) v = 0;
    else {
        int b = (idx - 1) / SCAN_B;
        v = rowptr[idx] + (b > 0 ? sb[b - 1] : 0);
    }
    rowptr[idx] = v;
    if (idx < n) cursor[idx] = v;
}

__global__ void scatter_kernel(const int* __restrict__ ei, int E, int n,
                               int* __restrict__ cursor,
                               int* __restrict__ csr_src) {
    __shared__ int s64;
    if (threadIdx.x == 0) s64 = block_detect_i64(ei);
    __syncthreads();
    int i = blockIdx.x * blockDim.x + threadIdx.x;
    if (i >= E + n) return;
    int s, d;
    if (i < E) {
        if (s64) {
            const long long* p = (const long long*)ei;
            s = (int)p[i];
            d = (int)p[(long long)E + i];
        } else {
            s = ei[i];
            d = ei[E + i];
        }
    } else {
        s = i - E;
        d = i - E;
    }
    int p = atomicAdd(&cursor[d], 1);
    csr_src[p] = s;
}

// ---------------------------------------------------------------------------
// Unified GEMM via mma.sync bf16 hi/lo split + fused attention logits.
// H is written as half2-packed uint32 (fp16 — only the aggregation reads it).
// CTA = 256 threads (8 warps); warp computes 16 rows x NCOLS, K = 128.
// ---------------------------------------------------------------------------
__device__ __forceinline__ void mma_bf16(float& c0, float& c1, float& c2, float& c3,
                                         uint32_t a0, uint32_t a1, uint32_t a2, uint32_t a3,
                                         uint32_t b0, uint32_t b1) {
    asm volatile(
        "mma.sync.aligned.m16n8k16.row.col.f32.bf16.bf16.f32 "
        "{%0,%1,%2,%3}, {%4,%5,%6,%7}, {%8,%9}, {%0,%1,%2,%3};"
        : "+f"(c0), "+f"(c1), "+f"(c2), "+f"(c3)
        : "r"(a0), "r"(a1), "r"(a2), "r"(a3), "r"(b0), "r"(b1));
}

template<int NCOLS, int HEADS>
__global__ void __launch_bounds__(256)
gemm_mma_kernel(const float* __restrict__ X,
                const uint32_t* __restrict__ whi,
                const uint32_t* __restrict__ wlo,
                const float* __restrict__ a_src,
                const float* __restrict__ a_dst,
                uint32_t* __restrict__ Hout,      // half2-packed, NCOLS/2 words/row
                float* __restrict__ es, float* __restrict__ ed, int n) {
    constexpr int NT = NCOLS / 8;
    constexpr int WWORDS = NCOLS * WSTR;
    extern __shared__ uint32_t smem_u[];
    uint32_t* sWhi = smem_u;
    uint32_t* sWlo = smem_u + WWORDS;
    float* sAs = (float*)(smem_u + 2 * WWORDS);
    float* sAd = sAs + NCOLS;

    const int tid = threadIdx.x;
    const int w = tid >> 5, lane = tid & 31;
    const int g = lane >> 2, t2 = lane & 3;

    for (int i = tid; i < WWORDS; i += 256) {
        sWhi[i] = whi[i];
        sWlo[i] = wlo[i];
    }
    if (tid < NCOLS) { sAs[tid] = a_src[tid]; sAd[tid] = a_dst[tid]; }
    __syncthreads();

    const int base = blockIdx.x * 128 + w * 16;
    const int r0 = base + g, r1 = base + g + 8;
    const bool v0 = r0 < n, v1 = r1 < n;
    const float* x0 = X + (size_t)r0 * 128;
    const float* x1 = X + (size_t)r1 * 128;

    float acc[NT][4];
    #pragma unroll
    for (int nt = 0; nt < NT; nt++)
        #pragma unroll
        for (int j = 0; j < 4; j++) acc[nt][j] = 0.f;

    #pragma unroll
    for (int ks = 0; ks < 8; ks++) {
        const int co = (ks * 8 + t2) * 2;     // fp32 column offset
        float2 f00 = v0 ? *(const float2*)&x0[co]     : make_float2(0.f, 0.f);
        float2 f02 = v0 ? *(const float2*)&x0[co + 8] : make_float2(0.f, 0.f);
        float2 f10 = v1 ? *(const float2*)&x1[co]     : make_float2(0.f, 0.f);
        float2 f12 = v1 ? *(const float2*)&x1[co + 8] : make_float2(0.f, 0.f);
        uint32_t ah0, al0, ah1, al1, ah2, al2, ah3, al3;
        split2(f00, ah0, al0);
        split2(f10, ah1, al1);
        split2(f02, ah2, al2);
        split2(f12, ah3, al3);
        #pragma unroll
        for (int nt = 0; nt < NT; nt++) {
            const int bidx = (nt * 8 + g) * WSTR + ks * 8 + t2;
            uint32_t bh0 = sWhi[bidx], bh1 = sWhi[bidx + 4];
            uint32_t bl0 = sWlo[bidx], bl1 = sWlo[bidx + 4];
            mma_bf16(acc[nt][0], acc[nt][1], acc[nt][2], acc[nt][3],
                     ah0, ah1, ah2, ah3, bh0, bh1);
            mma_bf16(acc[nt][0], acc[nt][1], acc[nt][2], acc[nt][3],
                     ah0, ah1, ah2, ah3, bl0, bl1);
            mma_bf16(acc[nt][0], acc[nt][1], acc[nt][2], acc[nt][3],
                     al0, al1, al2, al3, bh0, bh1);
        }
    }

    // Epilogue: write half2-packed H rows + fused per-head logits
    float ss0[HEADS], dd0[HEADS], ss1[HEADS], dd1[HEADS];
    #pragma unroll
    for (int h = 0; h < HEADS; h++) { ss0[h] = dd0[h] = ss1[h] = dd1[h] = 0.f; }
    #pragma unroll
    for (int nt = 0; nt < NT; nt++) {
        const int c = nt * 8 + t2 * 2;
        const int head = nt >> 2;          // 32 cols per head in both layers
        float as0 = sAs[c], as1 = sAs[c + 1];
        float ad0 = sAd[c], ad1 = sAd[c + 1];
        ss0[head] += acc[nt][0] * as0 + acc[nt][1] * as1;
        dd0[head] += acc[nt][0] * ad0 + acc[nt][1] * ad1;
        ss1[head] += acc[nt][2] * as0 + acc[nt][3] * as1;
        dd1[head] += acc[nt][2] * ad0 + acc[nt][3] * ad1;
        const int pidx = nt * 4 + t2;      // half2 word index within row
        if (v0) {
            __half2 p = __floats2half2_rn(acc[nt][0], acc[nt][1]);
            Hout[(size_t)r0 * (NCOLS / 2) + pidx] = *(uint32_t*)&p;
        }
        if (v1) {
            __half2 p = __floats2half2_rn(acc[nt][2], acc[nt][3]);
            Hout[(size_t)r1 * (NCOLS / 2) + pidx] = *(uint32_t*)&p;
        }
    }
    #pragma unroll
    for (int h = 0; h < HEADS; h++) {
        ss0[h] += __shfl_xor_sync(0xFFFFFFFF, ss0[h], 1);
        ss0[h] += __shfl_xor_sync(0xFFFFFFFF, ss0[h], 2);
        dd0[h] += __shfl_xor_sync(0xFFFFFFFF, dd0[h], 1);
        dd0[h] += __shfl_xor_sync(0xFFFFFFFF, dd0[h], 2);
        ss1[h] += __shfl_xor_sync(0xFFFFFFFF, ss1[h], 1);
        ss1[h] += __shfl_xor_sync(0xFFFFFFFF, ss1[h], 2);
        dd1[h] += __shfl_xor_sync(0xFFFFFFFF, dd1[h], 1);
        dd1[h] += __shfl_xor_sync(0xFFFFFFFF, dd1[h], 2);
    }
    if (t2 == 0) {
        if (v0) {
            #pragma unroll
            for (int h = 0; h < HEADS; h++) {
                es[r0 * HEADS + h] = ss0[h];
                ed[r0 * HEADS + h] = dd0[h];
            }
        }
        if (v1) {
            #pragma unroll
            for (int h = 0; h < HEADS; h++) {
                es[r1 * HEADS + h] = ss1[h];
                ed[r1 * HEADS + h] = dd1[h];
            }
        }
    }
}

// ---------------------------------------------------------------------------
// Fused layer-1 aggregation: warp per dst, fp16 h1 gather (256B/edge)
// ---------------------------------------------------------------------------
__global__ void agg1_kernel(const int* __restrict__ rowptr,
                            const int* __restrict__ csr_src,
                            const uint32_t* __restrict__ Hm,   // half2, 64 words/row
                            const float* __restrict__ es,
                            const float* __restrict__ ed,
                            const float* __restrict__ bias,
                            float* __restrict__ out, int n) {
    int d = (blockIdx.x * blockDim.x + threadIdx.x) >> 5;
    if (d >= n) return;
    int lane = threadIdx.x & 31;
    int head = lane >> 3;
    float edv = ed[d * H1 + head];
    float a0 = 0.f, a1 = 0.f, a2 = 0.f, a3 = 0.f, den = 0.f;
    int beg = rowptr[d], end = rowptr[d + 1];
    for (int base = beg; base < end; base += 32) {
        int e = base + lane;
        int sidx = (e < end) ? csr_src[e] : 0;
        int cnt = end - base; if (cnt > 32) cnt = 32;
        #pragma unroll 4
        for (int j = 0; j < cnt; j++) {
            int s = __shfl_sync(0xFFFFFFFF, sidx, j);
            float v = es[s * H1 + head] + edv;
            v = v > 0.f ? v : 0.2f * v;
            float ex = __expf(v);
            den += ex;
            uint2 hv = *(const uint2*)&Hm[(size_t)s * 64 + lane * 2];
            float2 p0 = __half22float2(*(__half2*)&hv.x);
            float2 p1 = __half22float2(*(__half2*)&hv.y);
            a0 += p0.x * ex; a1 += p0.y * ex; a2 += p1.x * ex; a3 += p1.y * ex;
        }
    }
    float inv = 1.0f / den;
    float4 bv = *(const float4*)&bias[lane * 4];
    float r0 = a0 * inv + bv.x;
    float r1 = a1 * inv + bv.y;
    float r2 = a2 * inv + bv.z;
    float r3 = a3 * inv + bv.w;
    r0 = r0 > 0.f ? r0 : expm1f(r0);
    r1 = r1 > 0.f ? r1 : expm1f(r1);
    r2 = r2 > 0.f ? r2 : expm1f(r2);
    r3 = r3 > 0.f ? r3 : expm1f(r3);
    *(float4*)&out[(size_t)d * F1 + lane * 4] = make_float4(r0, r1, r2, r3);
}

// Fused layer-2 aggregation: HALF-WARP per dst; lane owns 2 cols via one half2.
__global__ void agg2_kernel(const int* __restrict__ rowptr,
                            const int* __restrict__ csr_src,
                            const uint32_t* __restrict__ Hm,   // half2, 16 words/row
                            const float* __restrict__ es,
                            const float* __restrict__ ed,
                            const float* __restrict__ bias,
                            float* __restrict__ out, int n) {
    int d = (blockIdx.x * blockDim.x + threadIdx.x) >> 4;
    if (d >= n) return;
    int sl = threadIdx.x & 15;
    float edv = ed[d];
    float acc0 = 0.f, acc1 = 0.f, den = 0.f;
    int beg = rowptr[d], end = rowptr[d + 1];
    for (int base = beg; base < end; base += 16) {
        int e = base + sl;
        int sidx = (e < end) ? csr_src[e] : 0;
        int cnt = end - base; if (cnt > 16) cnt = 16;
        #pragma unroll 4
        for (int j = 0; j < cnt; j++) {
            int s = __shfl_sync(0xFFFFFFFF, sidx, j, 16);
            float v = es[s] + edv;
            v = v > 0.f ? v : 0.2f * v;
            float ex = __expf(v);
            den += ex;
            uint32_t hv = Hm[(size_t)s * 16 + sl];
            float2 p = __half22float2(*(__half2*)&hv);
            acc0 += p.x * ex; acc1 += p.y * ex;
        }
    }
    float inv = 1.0f / den;
    float2 bv = *(const float2*)&bias[sl * 2];
    *(float2*)&out[(size_t)d * OC2 + sl * 2] =
        make_float2(acc0 * inv + bv.x, acc1 * inv + bv.y);
}

// ---------------------------------------------------------------------------
// Launch
// ---------------------------------------------------------------------------
extern "C" void kernel_launch(void* const* d_in, const int* in_sizes, int n_in,
                              void* d_out, int out_size) {
    const float* x      = (const float*)d_in[0];
    const int*   ei     = (const int*)  d_in[1];
    const float* W1     = (const float*)d_in[2];
    const float* a_src1 = (const float*)d_in[3];
    const float* a_dst1 = (const float*)d_in[4];
    const float* b1     = (const float*)d_in[5];
    const float* W2     = (const float*)d_in[6];
    const float* a_src2 = (const float*)d_in[7];
    const float* a_dst2 = (const float*)d_in[8];
    const float* b2     = (const float*)d_in[9];
    float* out = (float*)d_out;

    int n = in_sizes[0] / 128;
    long long ee = in_sizes[1];
    int E = (int)(ee / 2);
    if (E > EMAX) E = (int)(ee / 4);
    int ET = E + n;
    int nblk = cdiv(n, SCAN_B);

    float *o1, *es1, *ed1, *es2, *ed2;
    uint32_t *h1, *h2, *w1hi, *w1lo, *w2hi, *w2lo;
    int *deg, *rowptr, *cursor, *csr, *bsum;
    cudaGetSymbolAddress((void**)&h1,  g_h1);
    cudaGetSymbolAddress((void**)&o1,  g_o1);
    cudaGetSymbolAddress((void**)&h2,  g_h2);
    cudaGetSymbolAddress((void**)&es1, g_es1);
    cudaGetSymbolAddress((void**)&ed1, g_ed1);
    cudaGetSymbolAddress((void**)&es2, g_es2);
    cudaGetSymbolAddress((void**)&ed2, g_ed2);
    cudaGetSymbolAddress((void**)&w1hi, g_w1hi);
    cudaGetSymbolAddress((void**)&w1lo, g_w1lo);
    cudaGetSymbolAddress((void**)&w2hi, g_w2hi);
    cudaGetSymbolAddress((void**)&w2lo, g_w2lo);
    cudaGetSymbolAddress((void**)&deg, g_deg);
    cudaGetSymbolAddress((void**)&rowptr, g_rowptr);
    cudaGetSymbolAddress((void**)&cursor, g_cursor);
    cudaGetSymbolAddress((void**)&csr, g_csr_src);
    cudaGetSymbolAddress((void**)&bsum, g_bsum);

    const int sm1 = (2 * 128 * WSTR + 2 * 128) * 4;
    const int sm2 = (2 * 32 * WSTR + 2 * 32) * 4;
    cudaFuncSetAttribute(gemm_mma_kernel<128, 4>,
                         cudaFuncAttributeMaxDynamicSharedMemorySize, sm1);
    cudaFuncSetAttribute(gemm_mma_kernel<32, 1>,
                         cudaFuncAttributeMaxDynamicSharedMemorySize, sm2);

    // -------- preprocessing (5 launches) --------
    prep_w_kernel<<<cdiv(NMAX, 256), 256>>>(W1, W2, w1hi, w1lo, w2hi, w2lo, deg, n);
    deg_kernel<<<cdiv(ET, 256), 256>>>(ei, E, n, deg);
    scan_block_kernel<<<nblk, SCAN_B>>>(deg, rowptr, bsum, n);
    finalize_rowptr_kernel<<<cdiv(n + 1, 256), 256>>>(rowptr, cursor, bsum, n, nblk);
    scatter_kernel<<<cdiv(ET, 256), 256>>>(ei, E, n, cursor, csr);

    // -------- layer 1 --------
    gemm_mma_kernel<128, 4><<<cdiv(n, 128), 256, sm1>>>(
        x, w1hi, w1lo, a_src1, a_dst1, h1, es1, ed1, n);
    agg1_kernel<<<cdiv(n * 32, 256), 256>>>(rowptr, csr, h1, es1, ed1, b1, o1, n);

    // -------- layer 2 --------
    gemm_mma_kernel<32, 1><<<cdiv(n, 128), 256, sm2>>>(
        o1, w2hi, w2lo, a_src2, a_dst2, h2, es2, ed2, n);
    agg2_kernel<<<cdiv(n * 16, 256), 256>>>(rowptr, csr, h2, es2, ed2, b2, out, n);
}

// round 9
// speedup vs baseline: 1.8921x; 1.0580x over previous
#include <cuda_runtime.h>
#include <cuda_bf16.h>
#include <cuda_fp16.h>
#include <math.h>
#include <stdint.h>

// ---------------------------------------------------------------------------
// Problem constants
// ---------------------------------------------------------------------------
#define NMAX   50176            // padded (50000 real)
#define EMAX   800000
#define ETMAX  (NMAX + EMAX)
#define F1     128
#define H1     4
#define OC2    32
#define WSTR   68               // padded uint32 row stride for B tiles in SMEM
#define SCAN_B 1024

// ---------------------------------------------------------------------------
// Scratch (device globals)
// ---------------------------------------------------------------------------
__device__ __align__(16) uint32_t g_h1 [NMAX * 64];   // h1 half2-packed (128 cols)
__device__ __align__(16) uint32_t g_o1 [NMAX * 64];   // layer1 out, half2-packed
__device__ __align__(16) uint32_t g_h2 [NMAX * 16];   // h2 half2-packed (32 cols)
__device__ __align__(16) float    g_es1[NMAX * H1];
__device__ __align__(16) float    g_ed1[NMAX * H1];
__device__ __align__(16) float    g_es2[NMAX];
__device__ __align__(16) float    g_ed2[NMAX];
__device__ __align__(16) uint32_t g_w1hi[128 * WSTR]; // W1^T hi, n-major padded
__device__ __align__(16) uint32_t g_w1lo[128 * WSTR];
__device__ __align__(16) uint32_t g_w2hi[32 * WSTR];  // W2^T hi
__device__ __align__(16) uint32_t g_w2lo[32 * WSTR];
__device__ int g_deg[NMAX];
__device__ int g_rowptr[NMAX + 1];
__device__ int g_cursor[NMAX];
__device__ int g_csr_src[ETMAX];
__device__ int g_bsum[64];

static inline int cdiv(int a, int b) { return (a + b - 1) / b; }

// ---------------------------------------------------------------------------
// bf16 hi/lo pack helpers
// ---------------------------------------------------------------------------
__device__ __forceinline__ uint32_t pack_bf2(float a, float b) {
    __nv_bfloat16 ha = __float2bfloat16(a), hb = __float2bfloat16(b);
    unsigned short ua = *(unsigned short*)&ha, ub = *(unsigned short*)&hb;
    return (uint32_t)ua | ((uint32_t)ub << 16);
}
__device__ __forceinline__ void split2(float2 v, uint32_t& hi, uint32_t& lo) {
    __nv_bfloat16 h0 = __float2bfloat16(v.x), h1b = __float2bfloat16(v.y);
    unsigned short u0 = *(unsigned short*)&h0, u1 = *(unsigned short*)&h1b;
    hi = (uint32_t)u0 | ((uint32_t)u1 << 16);
    lo = pack_bf2(v.x - __bfloat162float(h0), v.y - __bfloat162float(h1b));
}

// ---------------------------------------------------------------------------
// Preprocessing
// ---------------------------------------------------------------------------
__device__ __forceinline__ int block_detect_i64(const int* ei) {
    int any = 0;
    #pragma unroll 8
    for (int k = 1; k < 128; k += 2) any |= ei[k];
    return (any == 0) ? 1 : 0;
}

__global__ void prep_w_kernel(const float* __restrict__ W1,
                              const float* __restrict__ W2,
                              uint32_t* __restrict__ w1hi, uint32_t* __restrict__ w1lo,
                              uint32_t* __restrict__ w2hi, uint32_t* __restrict__ w2lo) {
    int i = blockIdx.x * blockDim.x + threadIdx.x;
    if (i < 128 * 64) {
        int nrow = i >> 6, kp = i & 63;
        float2 v = make_float2(W1[(2 * kp) * 128 + nrow], W1[(2 * kp + 1) * 128 + nrow]);
        uint32_t hi, lo; split2(v, hi, lo);
        w1hi[nrow * WSTR + kp] = hi;
        w1lo[nrow * WSTR + kp] = lo;
    } else if (i < 128 * 64 + 32 * 64) {
        int j = i - 128 * 64;
        int nrow = j >> 6, kp = j & 63;
        float2 v = make_float2(W2[(2 * kp) * 32 + nrow], W2[(2 * kp + 1) * 32 + nrow]);
        uint32_t hi, lo; split2(v, hi, lo);
        w2hi[nrow * WSTR + kp] = hi;
        w2lo[nrow * WSTR + kp] = lo;
    }
}

__global__ void deg_kernel(const int* __restrict__ ei, int E, int n,
                           int* __restrict__ deg) {
    __shared__ int s64;
    if (threadIdx.x == 0) s64 = block_detect_i64(ei);
    __syncthreads();
    int i = blockIdx.x * blockDim.x + threadIdx.x;
    if (i >= E + n) return;
    int d;
    if (i < E) {
        d = s64 ? (int)((const long long*)ei)[(long long)E + i] : ei[E + i];
    } else {
        d = i - E;
    }
    atomicAdd(&deg[d], 1);
}

__global__ void scan_block_kernel(const int* __restrict__ deg,
                                  int* __restrict__ rowptr,
                                  int* __restrict__ bsum, int n) {
    __shared__ int sh[SCAN_B];
    int i = blockIdx.x * SCAN_B + threadIdx.x;
    int v = (i < n) ? deg[i] : 0;
    sh[threadIdx.x] = v;
    __syncthreads();
    for (int off = 1; off < SCAN_B; off <<= 1) {
        int t = (threadIdx.x >= off) ? sh[threadIdx.x - off] : 0;
        __syncthreads();
        sh[threadIdx.x] += t;
        __syncthreads();
    }
    if (i < n) rowptr[i + 1] = sh[threadIdx.x];   // inclusive, pre-offset
    if (threadIdx.x == SCAN_B - 1) bsum[blockIdx.x] = sh[SCAN_B - 1];
}

// Finalize rowptr with in-block scan of block sums (fused partials pass)
__global__ void finalize_rowptr_kernel(int* __restrict__ rowptr,
                                       int* __restrict__ cursor,
                                       const int* __restrict__ bsum,
                                       int n, int nb) {
    __shared__ int sb[64];
    int t = threadIdx.x;
    if (t < 64) sb[t] = (t < nb) ? bsum[t] : 0;
    __syncthreads();
    #pragma unroll
    for (int off = 1; off < 64; off <<= 1) {
        int v = (t < 64 && t >= off) ? sb[t - off] : 0;
        __syncthreads();
        if (t < 64) sb[t] += v;
        __syncthreads();
    }
    int idx = blockIdx.x * blockDim.x + t;
    if (idx > n) return;
    int v;
    if (idx == 0) v = 0;
    else {
        int b = (idx - 1) / SCAN_B;
        v = rowptr[idx] + (b > 0 ? sb[b - 1] : 0);
    }
    rowptr[idx] = v;
    if (idx < n) cursor[idx] = v;
}

__global__ void scatter_kernel(const int* __restrict__ ei, int E, int n,
                               int* __restrict__ cursor,
                               int* __restrict__ csr_src) {
    __shared__ int s64;
    if (threadIdx.x == 0) s64 = block_detect_i64(ei);
    __syncthreads();
    int i = blockIdx.x * blockDim.x + threadIdx.x;
    if (i >= E + n) return;
    int s, d;
    if (i < E) {
        if (s64) {
            const long long* p = (const long long*)ei;
            s = (int)p[i];
            d = (int)p[(long long)E + i];
        } else {
            s = ei[i];
            d = ei[E + i];
        }
    } else {
        s = i - E;
        d = i - E;
    }
    int p = atomicAdd(&cursor[d], 1);
    csr_src[p] = s;
}

// ---------------------------------------------------------------------------
// Unified GEMM via mma.sync bf16 hi/lo split + fused attention logits.
// HALF_IN: X is half2-packed (fp16->bf16 hi/lo split is exact).
// CTA = 256 threads (8 warps); warp computes 16 rows x NCOLS, K = 128.
// ---------------------------------------------------------------------------
__device__ __forceinline__ void mma_bf16(float& c0, float& c1, float& c2, float& c3,
                                         uint32_t a0, uint32_t a1, uint32_t a2, uint32_t a3,
                                         uint32_t b0, uint32_t b1) {
    asm volatile(
        "mma.sync.aligned.m16n8k16.row.col.f32.bf16.bf16.f32 "
        "{%0,%1,%2,%3}, {%4,%5,%6,%7}, {%8,%9}, {%0,%1,%2,%3};"
        : "+f"(c0), "+f"(c1), "+f"(c2), "+f"(c3)
        : "r"(a0), "r"(a1), "r"(a2), "r"(a3), "r"(b0), "r"(b1));
}

template<int NCOLS, int HEADS, bool HALF_IN>
__global__ void __launch_bounds__(256)
gemm_mma_kernel(const void* __restrict__ Xv,
                const uint32_t* __restrict__ whi,
                const uint32_t* __restrict__ wlo,
                const float* __restrict__ a_src,
                const float* __restrict__ a_dst,
                uint32_t* __restrict__ Hout,      // half2-packed, NCOLS/2 words/row
                float* __restrict__ es, float* __restrict__ ed, int n) {
    constexpr int NT = NCOLS / 8;
    constexpr int WWORDS = NCOLS * WSTR;
    extern __shared__ uint32_t smem_u[];
    uint32_t* sWhi = smem_u;
    uint32_t* sWlo = smem_u + WWORDS;
    float* sAs = (float*)(smem_u + 2 * WWORDS);
    float* sAd = sAs + NCOLS;

    const int tid = threadIdx.x;
    const int w = tid >> 5, lane = tid & 31;
    const int g = lane >> 2, t2 = lane & 3;

    for (int i = tid; i < WWORDS; i += 256) {
        sWhi[i] = whi[i];
        sWlo[i] = wlo[i];
    }
    if (tid < NCOLS) { sAs[tid] = a_src[tid]; sAd[tid] = a_dst[tid]; }
    __syncthreads();

    const int base = blockIdx.x * 128 + w * 16;
    const int r0 = base + g, r1 = base + g + 8;
    const bool v0 = r0 < n, v1 = r1 < n;

    float acc[NT][4];
    #pragma unroll
    for (int nt = 0; nt < NT; nt++)
        #pragma unroll
        for (int j = 0; j < 4; j++) acc[nt][j] = 0.f;

    #pragma unroll
    for (int ks = 0; ks < 8; ks++) {
        const int wi = ks * 8 + t2;               // float2/half2 word index
        float2 f00, f02, f10, f12;
        if (HALF_IN) {
            const uint32_t* x0 = (const uint32_t*)Xv + (size_t)r0 * 64;
            const uint32_t* x1 = (const uint32_t*)Xv + (size_t)r1 * 64;
            uint32_t u00 = v0 ? x0[wi] : 0u, u02 = v0 ? x0[wi + 4] : 0u;
            uint32_t u10 = v1 ? x1[wi] : 0u, u12 = v1 ? x1[wi + 4] : 0u;
            f00 = __half22float2(*(__half2*)&u00);
            f02 = __half22float2(*(__half2*)&u02);
            f10 = __half22float2(*(__half2*)&u10);
            f12 = __half22float2(*(__half2*)&u12);
        } else {
            const float* x0 = (const float*)Xv + (size_t)r0 * 128;
            const float* x1 = (const float*)Xv + (size_t)r1 * 128;
            f00 = v0 ? *(const float2*)&x0[wi * 2]     : make_float2(0.f, 0.f);
            f02 = v0 ? *(const float2*)&x0[wi * 2 + 8] : make_float2(0.f, 0.f);
            f10 = v1 ? *(const float2*)&x1[wi * 2]     : make_float2(0.f, 0.f);
            f12 = v1 ? *(const float2*)&x1[wi * 2 + 8] : make_float2(0.f, 0.f);
        }
        uint32_t ah0, al0, ah1, al1, ah2, al2, ah3, al3;
        split2(f00, ah0, al0);
        split2(f10, ah1, al1);
        split2(f02, ah2, al2);
        split2(f12, ah3, al3);
        #pragma unroll
        for (int nt = 0; nt < NT; nt++) {
            const int bidx = (nt * 8 + g) * WSTR + ks * 8 + t2;
            uint32_t bh0 = sWhi[bidx], bh1 = sWhi[bidx + 4];
            uint32_t bl0 = sWlo[bidx], bl1 = sWlo[bidx + 4];
            mma_bf16(acc[nt][0], acc[nt][1], acc[nt][2], acc[nt][3],
                     ah0, ah1, ah2, ah3, bh0, bh1);
            mma_bf16(acc[nt][0], acc[nt][1], acc[nt][2], acc[nt][3],
                     ah0, ah1, ah2, ah3, bl0, bl1);
            mma_bf16(acc[nt][0], acc[nt][1], acc[nt][2], acc[nt][3],
                     al0, al1, al2, al3, bh0, bh1);
        }
    }

    // Epilogue: write half2-packed H rows + fused per-head logits
    float ss0[HEADS], dd0[HEADS], ss1[HEADS], dd1[HEADS];
    #pragma unroll
    for (int h = 0; h < HEADS; h++) { ss0[h] = dd0[h] = ss1[h] = dd1[h] = 0.f; }
    #pragma unroll
    for (int nt = 0; nt < NT; nt++) {
        const int c = nt * 8 + t2 * 2;
        const int head = nt >> 2;          // 32 cols per head in both layers
        float as0 = sAs[c], as1 = sAs[c + 1];
        float ad0 = sAd[c], ad1 = sAd[c + 1];
        ss0[head] += acc[nt][0] * as0 + acc[nt][1] * as1;
        dd0[head] += acc[nt][0] * ad0 + acc[nt][1] * ad1;
        ss1[head] += acc[nt][2] * as0 + acc[nt][3] * as1;
        dd1[head] += acc[nt][2] * ad0 + acc[nt][3] * ad1;
        const int pidx = nt * 4 + t2;      // half2 word index within row
        if (v0) {
            __half2 p = __floats2half2_rn(acc[nt][0], acc[nt][1]);
            Hout[(size_t)r0 * (NCOLS / 2) + pidx] = *(uint32_t*)&p;
        }
        if (v1) {
            __half2 p = __floats2half2_rn(acc[nt][2], acc[nt][3]);
            Hout[(size_t)r1 * (NCOLS / 2) + pidx] = *(uint32_t*)&p;
        }
    }
    #pragma unroll
    for (int h = 0; h < HEADS; h++) {
        ss0[h] += __shfl_xor_sync(0xFFFFFFFF, ss0[h], 1);
        ss0[h] += __shfl_xor_sync(0xFFFFFFFF, ss0[h], 2);
        dd0[h] += __shfl_xor_sync(0xFFFFFFFF, dd0[h], 1);
        dd0[h] += __shfl_xor_sync(0xFFFFFFFF, dd0[h], 2);
        ss1[h] += __shfl_xor_sync(0xFFFFFFFF, ss1[h], 1);
        ss1[h] += __shfl_xor_sync(0xFFFFFFFF, ss1[h], 2);
        dd1[h] += __shfl_xor_sync(0xFFFFFFFF, dd1[h], 1);
        dd1[h] += __shfl_xor_sync(0xFFFFFFFF, dd1[h], 2);
    }
    if (t2 == 0) {
        if (v0) {
            #pragma unroll
            for (int h = 0; h < HEADS; h++) {
                es[r0 * HEADS + h] = ss0[h];
                ed[r0 * HEADS + h] = dd0[h];
            }
        }
        if (v1) {
            #pragma unroll
            for (int h = 0; h < HEADS; h++) {
                es[r1 * HEADS + h] = ss1[h];
                ed[r1 * HEADS + h] = dd1[h];
            }
        }
    }
}

// ---------------------------------------------------------------------------
// Fused layer-1 aggregation: warp per dst; fp16 gather; writes o1 as fp16.
// ---------------------------------------------------------------------------
__global__ void agg1_kernel(const int* __restrict__ rowptr,
                            const int* __restrict__ csr_src,
                            const uint32_t* __restrict__ Hm,   // half2, 64 words/row
                            const float* __restrict__ es,
                            const float* __restrict__ ed,
                            const float* __restrict__ bias,
                            uint32_t* __restrict__ out, int n) {
    int d = (blockIdx.x * blockDim.x + threadIdx.x) >> 5;
    if (d >= n) return;
    int lane = threadIdx.x & 31;
    int head = lane >> 3;
    float edv = ed[d * H1 + head];
    float a0 = 0.f, a1 = 0.f, a2 = 0.f, a3 = 0.f, den = 0.f;
    int beg = rowptr[d], end = rowptr[d + 1];
    for (int base = beg; base < end; base += 32) {
        int e = base + lane;
        int sidx = (e < end) ? csr_src[e] : 0;
        int cnt = end - base; if (cnt > 32) cnt = 32;
        #pragma unroll 8
        for (int j = 0; j < cnt; j++) {
            int s = __shfl_sync(0xFFFFFFFF, sidx, j);
            float v = es[s * H1 + head] + edv;
            v = v > 0.f ? v : 0.2f * v;
            float ex = __expf(v);
            den += ex;
            uint2 hv = *(const uint2*)&Hm[(size_t)s * 64 + lane * 2];
            float2 p0 = __half22float2(*(__half2*)&hv.x);
            float2 p1 = __half22float2(*(__half2*)&hv.y);
            a0 += p0.x * ex; a1 += p0.y * ex; a2 += p1.x * ex; a3 += p1.y * ex;
        }
    }
    float inv = 1.0f / den;
    float4 bv = *(const float4*)&bias[lane * 4];
    float r0 = a0 * inv + bv.x;
    float r1 = a1 * inv + bv.y;
    float r2 = a2 * inv + bv.z;
    float r3 = a3 * inv + bv.w;
    r0 = r0 > 0.f ? r0 : expm1f(r0);
    r1 = r1 > 0.f ? r1 : expm1f(r1);
    r2 = r2 > 0.f ? r2 : expm1f(r2);
    r3 = r3 > 0.f ? r3 : expm1f(r3);
    __half2 p0 = __floats2half2_rn(r0, r1);
    __half2 p1 = __floats2half2_rn(r2, r3);
    uint2 pw = make_uint2(*(uint32_t*)&p0, *(uint32_t*)&p1);
    *(uint2*)&out[(size_t)d * 64 + lane * 2] = pw;
}

// Fused layer-2 aggregation: HALF-WARP per dst; lane owns 2 cols via one half2.
__global__ void agg2_kernel(const int* __restrict__ rowptr,
                            const int* __restrict__ csr_src,
                            const uint32_t* __restrict__ Hm,   // half2, 16 words/row
                            const float* __restrict__ es,
                            const float* __restrict__ ed,
                            const float* __restrict__ bias,
                            float* __restrict__ out, int n) {
    int d = (blockIdx.x * blockDim.x + threadIdx.x) >> 4;
    if (d >= n) return;
    int sl = threadIdx.x & 15;
    float edv = ed[d];
    float acc0 = 0.f, acc1 = 0.f, den = 0.f;
    int beg = rowptr[d], end = rowptr[d + 1];
    for (int base = beg; base < end; base += 16) {
        int e = base + sl;
        int sidx = (e < end) ? csr_src[e] : 0;
        int cnt = end - base; if (cnt > 16) cnt = 16;
        #pragma unroll 8
        for (int j = 0; j < cnt; j++) {
            int s = __shfl_sync(0xFFFFFFFF, sidx, j, 16);
            float v = es[s] + edv;
            v = v > 0.f ? v : 0.2f * v;
            float ex = __expf(v);
            den += ex;
            uint32_t hv = Hm[(size_t)s * 16 + sl];
            float2 p = __half22float2(*(__half2*)&hv);
            acc0 += p.x * ex; acc1 += p.y * ex;
        }
    }
    float inv = 1.0f / den;
    float2 bv = *(const float2*)&bias[sl * 2];
    *(float2*)&out[(size_t)d * OC2 + sl * 2] =
        make_float2(acc0 * inv + bv.x, acc1 * inv + bv.y);
}

// ---------------------------------------------------------------------------
// Launch — edge preprocessing forked onto a second stream, overlapping gemm1.
// ---------------------------------------------------------------------------
extern "C" void kernel_launch(void* const* d_in, const int* in_sizes, int n_in,
                              void* d_out, int out_size) {
    const float* x      = (const float*)d_in[0];
    const int*   ei     = (const int*)  d_in[1];
    const float* W1     = (const float*)d_in[2];
    const float* a_src1 = (const float*)d_in[3];
    const float* a_dst1 = (const float*)d_in[4];
    const float* b1     = (const float*)d_in[5];
    const float* W2     = (const float*)d_in[6];
    const float* a_src2 = (const float*)d_in[7];
    const float* a_dst2 = (const float*)d_in[8];
    const float* b2     = (const float*)d_in[9];
    float* out = (float*)d_out;

    int n = in_sizes[0] / 128;
    long long ee = in_sizes[1];
    int E = (int)(ee / 2);
    if (E > EMAX) E = (int)(ee / 4);
    int ET = E + n;
    int nblk = cdiv(n, SCAN_B);

    float *es1, *ed1, *es2, *ed2;
    uint32_t *h1, *o1, *h2, *w1hi, *w1lo, *w2hi, *w2lo;
    int *deg, *rowptr, *cursor, *csr, *bsum;
    cudaGetSymbolAddress((void**)&h1,  g_h1);
    cudaGetSymbolAddress((void**)&o1,  g_o1);
    cudaGetSymbolAddress((void**)&h2,  g_h2);
    cudaGetSymbolAddress((void**)&es1, g_es1);
    cudaGetSymbolAddress((void**)&ed1, g_ed1);
    cudaGetSymbolAddress((void**)&es2, g_es2);
    cudaGetSymbolAddress((void**)&ed2, g_ed2);
    cudaGetSymbolAddress((void**)&w1hi, g_w1hi);
    cudaGetSymbolAddress((void**)&w1lo, g_w1lo);
    cudaGetSymbolAddress((void**)&w2hi, g_w2hi);
    cudaGetSymbolAddress((void**)&w2lo, g_w2lo);
    cudaGetSymbolAddress((void**)&deg, g_deg);
    cudaGetSymbolAddress((void**)&rowptr, g_rowptr);
    cudaGetSymbolAddress((void**)&cursor, g_cursor);
    cudaGetSymbolAddress((void**)&csr, g_csr_src);
    cudaGetSymbolAddress((void**)&bsum, g_bsum);

    const int sm1 = (2 * 128 * WSTR + 2 * 128) * 4;
    const int sm2 = (2 * 32 * WSTR + 2 * 32) * 4;
    cudaFuncSetAttribute((const void*)gemm_mma_kernel<128, 4, false>,
                         cudaFuncAttributeMaxDynamicSharedMemorySize, sm1);
    cudaFuncSetAttribute((const void*)gemm_mma_kernel<32, 1, true>,
                         cudaFuncAttributeMaxDynamicSharedMemorySize, sm2);

    // Side stream + fork/join events (created once; host-side objects only).
    static cudaStream_t s2 = nullptr;
    static cudaEvent_t evF = nullptr, evJ = nullptr;
    if (s2 == nullptr) {
        cudaStreamCreateWithFlags(&s2, cudaStreamNonBlocking);
        cudaEventCreateWithFlags(&evF, cudaEventDisableTiming);
        cudaEventCreateWithFlags(&evJ, cudaEventDisableTiming);
    }

    // ---- fork: CSR build on s2, concurrent with W prep + gemm1 on main ----
    cudaEventRecord(evF, 0);
    cudaStreamWaitEvent(s2, evF, 0);
    cudaMemsetAsync(deg, 0, (size_t)n * sizeof(int), s2);
    deg_kernel<<<cdiv(ET, 256), 256, 0, s2>>>(ei, E, n, deg);
    scan_block_kernel<<<nblk, SCAN_B, 0, s2>>>(deg, rowptr, bsum, n);
    finalize_rowptr_kernel<<<cdiv(n + 1, 256), 256, 0, s2>>>(rowptr, cursor, bsum, n, nblk);
    scatter_kernel<<<cdiv(ET, 256), 256, 0, s2>>>(ei, E, n, cursor, csr);
    cudaEventRecord(evJ, s2);

    prep_w_kernel<<<cdiv(128 * 64 + 32 * 64, 256), 256>>>(W1, W2, w1hi, w1lo, w2hi, w2lo);
    gemm_mma_kernel<128, 4, false><<<cdiv(n, 128), 256, sm1>>>(
        x, w1hi, w1lo, a_src1, a_dst1, h1, es1, ed1, n);

    // ---- join ----
    cudaStreamWaitEvent(0, evJ, 0);

    agg1_kernel<<<cdiv(n * 32, 256), 256>>>(rowptr, csr, h1, es1, ed1, b1, o1, n);
    gemm_mma_kernel<32, 1, true><<<cdiv(n, 128), 256, sm2>>>(
        o1, w2hi, w2lo, a_src2, a_dst2, h2, es2, ed2, n);
    agg2_kernel<<<cdiv(n * 16, 256), 256>>>(rowptr, csr, h2, es2, ed2, b2, out, n);
}